// round 13
// baseline (speedup 1.0000x reference)
#include <cuda_runtime.h>
#include <cuda_bf16.h>

#define GDIM 128
#define NRAYS 2048
#define NSAMP 128
#define VD 28
#define BTHREADS 256
#define BWARPS 8
#define SAMP_PER_WARP (NSAMP / BWARPS)   // 16
#define NSM 148
#define BLOCKS_PER_SM 6
#define NBLOCKS (NSM * BLOCKS_PER_SM)    // 888 = one full wave

// Constant corner offsets (floats). Valid because sample positions lie in
// [0, G-2): floor(p) in [0,125], floor(p)+1 <= 126 <= G-1, so the reference's
// clamps are identity and z/y/x neighbor strides are fixed.
#define DZ (VD)                  // 28
#define DY (GDIM * VD)           // 3584
#define DX (GDIM * GDIM * VD)    // 458752

// SH constants
#define Y00f 0.28209479177387814f
#define H3f  0.4886025119029199f
#define H15f 1.0925484305920792f
#define Q5f  0.31539156525252005f
#define Q15f 0.5462742152960396f

__global__ __launch_bounds__(BTHREADS, BLOCKS_PER_SM) void plenoxel_kernel(
    const float* __restrict__ grid,   // (G,G,G,28)
    const float* __restrict__ pos,    // (R,S,3)
    const float* __restrict__ dist,   // (R,S)
    const float* __restrict__ ang,    // (R,2)
    float* __restrict__ out)          // (R,3)
{
    const int tid  = threadIdx.x;
    const int lane = tid & 31;
    const int wid  = tid >> 5;

    __shared__ float spos[NSAMP * 3];
    __shared__ float sdist[NSAMP];
    __shared__ float Ysh[9];
    __shared__ float att_s[NSAMP];
    __shared__ float rgb_s[NSAMP][3];
    __shared__ float warp_att[4];
    __shared__ float warp_rgb[4][3];

    // Per-lane SH channel mapping (ray-independent parts)
    const bool act = (lane >= 1 && lane < VD);
    const int  j   = act ? (lane - 1) % 9 : 9;
    const int  g   = act ? (lane - 1) / 9 : 0;

    // Guards for the segmented 9-wide reduction tree (offsets 8,4,2,1)
    const bool p8 = act && (j == 0);
    const bool p4 = act && (j < 4);
    const bool p2 = act && (j < 2);
    const bool p1 = act && (j == 0);
    const bool pstore = act && (j == 0);   // lanes 1,10,19 hold final sums

    // Lane-channel for loads: clamp lanes 28-31 to channel 27 (redundant
    // loads, same cache lines) so no predication bubble on the LDG stream.
    const int lch = min(lane, VD - 1);

    // ---- Persistent: one wave of 888 blocks grid-strides over 2048 rays ----
    for (int r = blockIdx.x; r < NRAYS; r += NBLOCKS) {

        // Stage per-ray sample data coalesced
        for (int i = tid; i < NSAMP * 3; i += BTHREADS)
            spos[i] = pos[r * NSAMP * 3 + i];
        for (int i = tid; i < NSAMP; i += BTHREADS)
            sdist[i] = dist[r * NSAMP + i];
        if (tid == 0) {
            float th = ang[2 * r + 0];
            float ph = ang[2 * r + 1];
            float st, ct, sp, cp;
            sincosf(th, &st, &ct);
            sincosf(ph, &sp, &cp);
            float stcp = st * cp;
            float stsp = st * sp;
            Ysh[0] = Y00f;
            Ysh[1] = H3f * stsp;
            Ysh[2] = H3f * ct;
            Ysh[3] = H3f * stcp;
            Ysh[4] = H15f * stcp * stsp;
            Ysh[5] = H15f * stsp * ct;
            Ysh[6] = Q5f * (3.0f * ct * ct - 1.0f);
            Ysh[7] = H15f * stcp * ct;
            Ysh[8] = Q15f * (stcp * stcp - stsp * stsp);
        }
        __syncthreads();

        float ycoef = 0.0f;
        if (act) ycoef = Ysh[j];

        // ---- Gather pass: two samples per iteration (16 LDGs in flight),
        //      constant corner offsets (no clamps needed on this domain) ----
#pragma unroll
        for (int i = 0; i < SAMP_PER_WARP; i += 2) {
            const int s0 = wid * SAMP_PER_WARP + i;
            const int s1 = s0 + 1;

            const float pxA = spos[3 * s0 + 0], pyA = spos[3 * s0 + 1], pzA = spos[3 * s0 + 2];
            const float pxB = spos[3 * s1 + 0], pyB = spos[3 * s1 + 1], pzB = spos[3 * s1 + 2];

            const int ixA = (int)floorf(pxA), iyA = (int)floorf(pyA), izA = (int)floorf(pzA);
            const float fxA = pxA - (float)ixA, fyA = pyA - (float)iyA, fzA = pzA - (float)izA;
            const int ixB = (int)floorf(pxB), iyB = (int)floorf(pyB), izB = (int)floorf(pzB);
            const float fxB = pxB - (float)ixB, fyB = pyB - (float)iyB, fzB = pzB - (float)izB;

            const int baseA = ((ixA * GDIM + iyA) * GDIM + izA) * VD + lch;
            const int baseB = ((ixB * GDIM + iyB) * GDIM + izB) * VD + lch;

            // --- issue all 16 loads back-to-back; offsets are immediates ---
            const float* gA = grid + baseA;
            const float* gB = grid + baseB;
            const float a0 = __ldg(gA);
            const float a1 = __ldg(gA + DZ);
            const float a2 = __ldg(gA + DY);
            const float a3 = __ldg(gA + DY + DZ);
            const float a4 = __ldg(gA + DX);
            const float a5 = __ldg(gA + DX + DZ);
            const float a6 = __ldg(gA + DX + DY);
            const float a7 = __ldg(gA + DX + DY + DZ);
            const float b0 = __ldg(gB);
            const float b1 = __ldg(gB + DZ);
            const float b2 = __ldg(gB + DY);
            const float b3 = __ldg(gB + DY + DZ);
            const float b4 = __ldg(gB + DX);
            const float b5 = __ldg(gB + DX + DZ);
            const float b6 = __ldg(gB + DX + DY);
            const float b7 = __ldg(gB + DX + DY + DZ);

            // --- trilinear combine ---
            const float featsA =
                (1.0f - fxA) * ((1.0f - fyA) * ((1.0f - fzA) * a0 + fzA * a1)
                              +         fyA  * ((1.0f - fzA) * a2 + fzA * a3)) +
                        fxA  * ((1.0f - fyA) * ((1.0f - fzA) * a4 + fzA * a5)
                              +         fyA  * ((1.0f - fzA) * a6 + fzA * a7));
            const float featsB =
                (1.0f - fxB) * ((1.0f - fyB) * ((1.0f - fzB) * b0 + fzB * b1)
                              +         fyB  * ((1.0f - fzB) * b2 + fzB * b3)) +
                        fxB  * ((1.0f - fyB) * ((1.0f - fzB) * b4 + fzB * b5)
                              +         fyB  * ((1.0f - fzB) * b6 + fzB * b7));

            // att from channel 0
            const float sigmaA = __shfl_sync(0xffffffffu, featsA, 0);
            const float sigmaB = __shfl_sync(0xffffffffu, featsB, 0);
            if (lane == 0) {
                att_s[s0] = __expf(-sigmaA * sdist[s0]);
                att_s[s1] = __expf(-sigmaB * sdist[s1]);
            }

            // Segmented reduction: three 9-wide groups (lanes 1-9,10-18,19-27)
            float tA = featsA * ycoef;
            float tB = featsB * ycoef;
            float uA, uB;
            uA = __shfl_down_sync(0xffffffffu, tA, 8);
            uB = __shfl_down_sync(0xffffffffu, tB, 8);
            if (p8) { tA += uA; tB += uB; }
            uA = __shfl_down_sync(0xffffffffu, tA, 4);
            uB = __shfl_down_sync(0xffffffffu, tB, 4);
            if (p4) { tA += uA; tB += uB; }
            uA = __shfl_down_sync(0xffffffffu, tA, 2);
            uB = __shfl_down_sync(0xffffffffu, tB, 2);
            if (p2) { tA += uA; tB += uB; }
            uA = __shfl_down_sync(0xffffffffu, tA, 1);
            uB = __shfl_down_sync(0xffffffffu, tB, 1);
            if (p1) { tA += uA; tB += uB; }
            if (pstore) {
                rgb_s[s0][g] = tA;               // lanes 1,10,19 -> R,G,B
                rgb_s[s1][g] = tB;
            }
        }
        __syncthreads();

        // ---- 128-wide inclusive scan of att -> weight; reduce weighted rgb ----
        float x = 0.0f, att = 0.0f;
        if (tid < NSAMP) {
            att = att_s[tid];
            x   = att;
        }
#pragma unroll
        for (int o = 1; o < 32; o <<= 1) {
            float ysh = __shfl_up_sync(0xffffffffu, x, o);
            if (lane >= o) x += ysh;
        }
        if (tid < NSAMP && lane == 31) warp_att[wid] = x;
        __syncthreads();

        float vr = 0.0f, vg = 0.0f, vb = 0.0f;
        if (tid < NSAMP) {
            float offset = 0.0f;
#pragma unroll
            for (int i = 0; i < 3; i++)
                if (i < wid) offset += warp_att[i];
            const float trans  = x + offset;
            const float weight = trans * (1.0f - att);
            vr = weight * rgb_s[tid][0];
            vg = weight * rgb_s[tid][1];
            vb = weight * rgb_s[tid][2];
        }
#pragma unroll
        for (int o = 16; o > 0; o >>= 1) {
            vr += __shfl_down_sync(0xffffffffu, vr, o);
            vg += __shfl_down_sync(0xffffffffu, vg, o);
            vb += __shfl_down_sync(0xffffffffu, vb, o);
        }
        if (tid < NSAMP && lane == 0) {
            warp_rgb[wid][0] = vr;
            warp_rgb[wid][1] = vg;
            warp_rgb[wid][2] = vb;
        }
        __syncthreads();

        if (tid == 0) {
            float R = 0.0f, Gg = 0.0f, B = 0.0f;
#pragma unroll
            for (int i = 0; i < 4; i++) {
                R  += warp_rgb[i][0];
                Gg += warp_rgb[i][1];
                B  += warp_rgb[i][2];
            }
            out[3 * r + 0] = R;
            out[3 * r + 1] = Gg;
            out[3 * r + 2] = B;
        }
        __syncthreads();   // protect smem reuse across ray iterations
    }
}

extern "C" void kernel_launch(void* const* d_in, const int* in_sizes, int n_in,
                              void* d_out, int out_size) {
    const float* grid = (const float*)d_in[0];
    const float* pos  = (const float*)d_in[1];
    const float* dst  = (const float*)d_in[2];
    const float* ang  = (const float*)d_in[3];
    float* out = (float*)d_out;
    plenoxel_kernel<<<NBLOCKS, BTHREADS>>>(grid, pos, dst, ang, out);
}

// round 17
// speedup vs baseline: 1.2511x; 1.2511x over previous
#include <cuda_runtime.h>
#include <cuda_bf16.h>

#define GDIM 128
#define NRAYS 2048
#define NSAMP 128
#define VD 28
#define BTHREADS 256
#define BWARPS 8
#define SAMP_PER_WARP (NSAMP / BWARPS)   // 16

// Constant corner offsets (floats). Valid because sample positions lie in
// [0, G-2): floor(p) in [0,125], floor(p)+1 <= 126 <= G-1, so the reference's
// clamps are identity and z/y/x neighbor strides are fixed.
#define DZ (VD)                  // 28
#define DY (GDIM * VD)           // 3584
#define DX (GDIM * GDIM * VD)    // 458752

// SH constants
#define Y00f 0.28209479177387814f
#define H3f  0.4886025119029199f
#define H15f 1.0925484305920792f
#define Q5f  0.31539156525252005f
#define Q15f 0.5462742152960396f

__global__ __launch_bounds__(BTHREADS, 4) void plenoxel_kernel(
    const float* __restrict__ grid,   // (G,G,G,28)
    const float* __restrict__ pos,    // (R,S,3)
    const float* __restrict__ dist,   // (R,S)
    const float* __restrict__ ang,    // (R,2)
    float* __restrict__ out)          // (R,3)
{
    const int r    = blockIdx.x;
    const int tid  = threadIdx.x;
    const int lane = tid & 31;
    const int wid  = tid >> 5;

    __shared__ float spos[NSAMP * 3];
    __shared__ float sdist[NSAMP];
    __shared__ float Ysh[9];
    __shared__ float att_s[NSAMP];
    __shared__ float rgb_s[NSAMP][3];
    __shared__ float warp_att[4];
    __shared__ float warp_rgb[4][3];

    // Stage per-ray sample data coalesced
    for (int i = tid; i < NSAMP * 3; i += BTHREADS)
        spos[i] = pos[r * NSAMP * 3 + i];
    for (int i = tid; i < NSAMP; i += BTHREADS)
        sdist[i] = dist[r * NSAMP + i];
    if (tid == 0) {
        float th = ang[2 * r + 0];
        float ph = ang[2 * r + 1];
        float st, ct, sp, cp;
        sincosf(th, &st, &ct);
        sincosf(ph, &sp, &cp);
        float stcp = st * cp;
        float stsp = st * sp;
        Ysh[0] = Y00f;
        Ysh[1] = H3f * stsp;
        Ysh[2] = H3f * ct;
        Ysh[3] = H3f * stcp;
        Ysh[4] = H15f * stcp * stsp;
        Ysh[5] = H15f * stsp * ct;
        Ysh[6] = Q5f * (3.0f * ct * ct - 1.0f);
        Ysh[7] = H15f * stcp * ct;
        Ysh[8] = Q15f * (stcp * stcp - stsp * stsp);
    }
    __syncthreads();

    // Per-lane SH coefficient; lane = feature channel.
    const bool act = (lane >= 1 && lane < VD);
    const int  j   = act ? (lane - 1) % 9 : 9;
    const int  g   = act ? (lane - 1) / 9 : 0;
    float ycoef = 0.0f;
    if (act) ycoef = Ysh[j];

    // Guards for the segmented 9-wide reduction tree (offsets 8,4,2,1)
    const bool p8 = act && (j == 0);
    const bool p4 = act && (j < 4);
    const bool p2 = act && (j < 2);
    const bool p1 = act && (j == 0);
    const bool pstore = act && (j == 0);   // lanes 1,10,19 hold final sums

    // Lane-channel for loads: clamp lanes 28-31 to channel 27 (redundant
    // loads, same cache lines) so no predication bubble on the LDG stream.
    const int lch = min(lane, VD - 1);

    // ---- Gather pass: FOUR samples per iteration, all 32 LDGs issued
    //      back-to-back before any dependent math or shuffle (forces MLP=32) ----
#pragma unroll
    for (int i = 0; i < SAMP_PER_WARP; i += 4) {
        const int s0 = wid * SAMP_PER_WARP + i;
        const int s1 = s0 + 1;
        const int s2 = s0 + 2;
        const int s3 = s0 + 3;

        const float pxA = spos[3 * s0 + 0], pyA = spos[3 * s0 + 1], pzA = spos[3 * s0 + 2];
        const float pxB = spos[3 * s1 + 0], pyB = spos[3 * s1 + 1], pzB = spos[3 * s1 + 2];
        const float pxC = spos[3 * s2 + 0], pyC = spos[3 * s2 + 1], pzC = spos[3 * s2 + 2];
        const float pxD = spos[3 * s3 + 0], pyD = spos[3 * s3 + 1], pzD = spos[3 * s3 + 2];

        const int ixA = (int)floorf(pxA), iyA = (int)floorf(pyA), izA = (int)floorf(pzA);
        const int ixB = (int)floorf(pxB), iyB = (int)floorf(pyB), izB = (int)floorf(pzB);
        const int ixC = (int)floorf(pxC), iyC = (int)floorf(pyC), izC = (int)floorf(pzC);
        const int ixD = (int)floorf(pxD), iyD = (int)floorf(pyD), izD = (int)floorf(pzD);
        const float fxA = pxA - (float)ixA, fyA = pyA - (float)iyA, fzA = pzA - (float)izA;
        const float fxB = pxB - (float)ixB, fyB = pyB - (float)iyB, fzB = pzB - (float)izB;
        const float fxC = pxC - (float)ixC, fyC = pyC - (float)iyC, fzC = pzC - (float)izC;
        const float fxD = pxD - (float)ixD, fyD = pyD - (float)iyD, fzD = pzD - (float)izD;

        const float* gA = grid + ((ixA * GDIM + iyA) * GDIM + izA) * VD + lch;
        const float* gB = grid + ((ixB * GDIM + iyB) * GDIM + izB) * VD + lch;
        const float* gC = grid + ((ixC * GDIM + iyC) * GDIM + izC) * VD + lch;
        const float* gD = grid + ((ixD * GDIM + iyD) * GDIM + izD) * VD + lch;

        // --- 32 loads back-to-back; offsets are immediates ---
        const float a0 = __ldg(gA);
        const float a1 = __ldg(gA + DZ);
        const float a2 = __ldg(gA + DY);
        const float a3 = __ldg(gA + DY + DZ);
        const float a4 = __ldg(gA + DX);
        const float a5 = __ldg(gA + DX + DZ);
        const float a6 = __ldg(gA + DX + DY);
        const float a7 = __ldg(gA + DX + DY + DZ);
        const float b0 = __ldg(gB);
        const float b1 = __ldg(gB + DZ);
        const float b2 = __ldg(gB + DY);
        const float b3 = __ldg(gB + DY + DZ);
        const float b4 = __ldg(gB + DX);
        const float b5 = __ldg(gB + DX + DZ);
        const float b6 = __ldg(gB + DX + DY);
        const float b7 = __ldg(gB + DX + DY + DZ);
        const float c0 = __ldg(gC);
        const float c1 = __ldg(gC + DZ);
        const float c2 = __ldg(gC + DY);
        const float c3 = __ldg(gC + DY + DZ);
        const float c4 = __ldg(gC + DX);
        const float c5 = __ldg(gC + DX + DZ);
        const float c6 = __ldg(gC + DX + DY);
        const float c7 = __ldg(gC + DX + DY + DZ);
        const float d0 = __ldg(gD);
        const float d1 = __ldg(gD + DZ);
        const float d2 = __ldg(gD + DY);
        const float d3 = __ldg(gD + DY + DZ);
        const float d4 = __ldg(gD + DX);
        const float d5 = __ldg(gD + DX + DZ);
        const float d6 = __ldg(gD + DX + DY);
        const float d7 = __ldg(gD + DX + DY + DZ);

        // --- trilinear combines (a*/b* consumed first frees regs early) ---
        const float featsA =
            (1.0f - fxA) * ((1.0f - fyA) * ((1.0f - fzA) * a0 + fzA * a1)
                          +         fyA  * ((1.0f - fzA) * a2 + fzA * a3)) +
                    fxA  * ((1.0f - fyA) * ((1.0f - fzA) * a4 + fzA * a5)
                          +         fyA  * ((1.0f - fzA) * a6 + fzA * a7));
        const float featsB =
            (1.0f - fxB) * ((1.0f - fyB) * ((1.0f - fzB) * b0 + fzB * b1)
                          +         fyB  * ((1.0f - fzB) * b2 + fzB * b3)) +
                    fxB  * ((1.0f - fyB) * ((1.0f - fzB) * b4 + fzB * b5)
                          +         fyB  * ((1.0f - fzB) * b6 + fzB * b7));
        const float featsC =
            (1.0f - fxC) * ((1.0f - fyC) * ((1.0f - fzC) * c0 + fzC * c1)
                          +         fyC  * ((1.0f - fzC) * c2 + fzC * c3)) +
                    fxC  * ((1.0f - fyC) * ((1.0f - fzC) * c4 + fzC * c5)
                          +         fyC  * ((1.0f - fzC) * c6 + fzC * c7));
        const float featsD =
            (1.0f - fxD) * ((1.0f - fyD) * ((1.0f - fzD) * d0 + fzD * d1)
                          +         fyD  * ((1.0f - fzD) * d2 + fzD * d3)) +
                    fxD  * ((1.0f - fyD) * ((1.0f - fzD) * d4 + fzD * d5)
                          +         fyD  * ((1.0f - fzD) * d6 + fzD * d7));

        // att from channel 0
        const float sigmaA = __shfl_sync(0xffffffffu, featsA, 0);
        const float sigmaB = __shfl_sync(0xffffffffu, featsB, 0);
        const float sigmaC = __shfl_sync(0xffffffffu, featsC, 0);
        const float sigmaD = __shfl_sync(0xffffffffu, featsD, 0);
        if (lane == 0) {
            att_s[s0] = __expf(-sigmaA * sdist[s0]);
            att_s[s1] = __expf(-sigmaB * sdist[s1]);
            att_s[s2] = __expf(-sigmaC * sdist[s2]);
            att_s[s3] = __expf(-sigmaD * sdist[s3]);
        }

        // Segmented reduction: three 9-wide groups (lanes 1-9,10-18,19-27),
        // four samples interleaved.
        float tA = featsA * ycoef;
        float tB = featsB * ycoef;
        float tC = featsC * ycoef;
        float tD = featsD * ycoef;
        float uA, uB, uC, uD;
        uA = __shfl_down_sync(0xffffffffu, tA, 8);
        uB = __shfl_down_sync(0xffffffffu, tB, 8);
        uC = __shfl_down_sync(0xffffffffu, tC, 8);
        uD = __shfl_down_sync(0xffffffffu, tD, 8);
        if (p8) { tA += uA; tB += uB; tC += uC; tD += uD; }
        uA = __shfl_down_sync(0xffffffffu, tA, 4);
        uB = __shfl_down_sync(0xffffffffu, tB, 4);
        uC = __shfl_down_sync(0xffffffffu, tC, 4);
        uD = __shfl_down_sync(0xffffffffu, tD, 4);
        if (p4) { tA += uA; tB += uB; tC += uC; tD += uD; }
        uA = __shfl_down_sync(0xffffffffu, tA, 2);
        uB = __shfl_down_sync(0xffffffffu, tB, 2);
        uC = __shfl_down_sync(0xffffffffu, tC, 2);
        uD = __shfl_down_sync(0xffffffffu, tD, 2);
        if (p2) { tA += uA; tB += uB; tC += uC; tD += uD; }
        uA = __shfl_down_sync(0xffffffffu, tA, 1);
        uB = __shfl_down_sync(0xffffffffu, tB, 1);
        uC = __shfl_down_sync(0xffffffffu, tC, 1);
        uD = __shfl_down_sync(0xffffffffu, tD, 1);
        if (p1) { tA += uA; tB += uB; tC += uC; tD += uD; }
        if (pstore) {
            rgb_s[s0][g] = tA;               // lanes 1,10,19 -> R,G,B
            rgb_s[s1][g] = tB;
            rgb_s[s2][g] = tC;
            rgb_s[s3][g] = tD;
        }
    }
    __syncthreads();

    // ---- 128-wide inclusive scan of att -> weight; reduce weighted rgb ----
    float x = 0.0f, att = 0.0f;
    if (tid < NSAMP) {
        att = att_s[tid];
        x   = att;
    }
#pragma unroll
    for (int o = 1; o < 32; o <<= 1) {
        float ysh = __shfl_up_sync(0xffffffffu, x, o);
        if (lane >= o) x += ysh;
    }
    if (tid < NSAMP && lane == 31) warp_att[wid] = x;
    __syncthreads();

    float vr = 0.0f, vg = 0.0f, vb = 0.0f;
    if (tid < NSAMP) {
        float offset = 0.0f;
#pragma unroll
        for (int i = 0; i < 3; i++)
            if (i < wid) offset += warp_att[i];
        const float trans  = x + offset;
        const float weight = trans * (1.0f - att);
        vr = weight * rgb_s[tid][0];
        vg = weight * rgb_s[tid][1];
        vb = weight * rgb_s[tid][2];
    }
#pragma unroll
    for (int o = 16; o > 0; o >>= 1) {
        vr += __shfl_down_sync(0xffffffffu, vr, o);
        vg += __shfl_down_sync(0xffffffffu, vg, o);
        vb += __shfl_down_sync(0xffffffffu, vb, o);
    }
    if (tid < NSAMP && lane == 0) {
        warp_rgb[wid][0] = vr;
        warp_rgb[wid][1] = vg;
        warp_rgb[wid][2] = vb;
    }
    __syncthreads();

    if (tid == 0) {
        float R = 0.0f, Gg = 0.0f, B = 0.0f;
#pragma unroll
        for (int i = 0; i < 4; i++) {
            R  += warp_rgb[i][0];
            Gg += warp_rgb[i][1];
            B  += warp_rgb[i][2];
        }
        out[3 * r + 0] = R;
        out[3 * r + 1] = Gg;
        out[3 * r + 2] = B;
    }
}

extern "C" void kernel_launch(void* const* d_in, const int* in_sizes, int n_in,
                              void* d_out, int out_size) {
    const float* grid = (const float*)d_in[0];
    const float* pos  = (const float*)d_in[1];
    const float* dst  = (const float*)d_in[2];
    const float* ang  = (const float*)d_in[3];
    float* out = (float*)d_out;
    plenoxel_kernel<<<NRAYS, BTHREADS>>>(grid, pos, dst, ang, out);
}